// round 13
// baseline (speedup 1.0000x reference)
#include <cuda_runtime.h>

#define PP    35
#define CIN   7
#define C1    16
#define A1C   32
#define C2    64
#define A2C   128
#define C3    128
#define DD    10
#define HH    200
#define WWG   176
#define VMAX  20000
#define NBUCK 64
#define NCH   (C1 + C2 + C3)   // 208
#define NP1   20
#define NGRP  4
#define GT    128              // threads per group (4 warps)
#define T2V   (NGRP * GT)      // 512
#define GRID2 148
#define NSTREAM (GRID2 * NGRP) // 592

typedef unsigned long long ull;

// ---------------- scratch ---------------------------------------------------------
__device__ float  g_h2[(size_t)VMAX * PP * C2];    // pre-BN h2
__device__ float  g_keep[(size_t)VMAX * PP];
__device__ float  g_max3[(size_t)VMAX * C3];
__device__ float  g_min3[(size_t)VMAX * C3];
__device__ double g_sumB [NBUCK][NCH];
__device__ double g_sqB  [NBUCK][NCH];
__device__ float  g_scale[NCH];
__device__ float  g_shift[NCH];

// ---------------- f32x2 helpers ----------------------------------------------------
__device__ __forceinline__ ull pack2(float lo, float hi) {
    ull r;
    asm("mov.b64 %0, {%1, %2};" : "=l"(r) : "f"(lo), "f"(hi));
    return r;
}
__device__ __forceinline__ float2 unpack2(ull v) {
    float2 r;
    asm("mov.b64 {%0, %1}, %2;" : "=f"(r.x), "=f"(r.y) : "l"(v));
    return r;
}
__device__ __forceinline__ void fma2(ull& d, ull a, ull b) {
    asm("fma.rn.f32x2 %0, %1, %2, %0;" : "+l"(d) : "l"(a), "l"(b));
}
__device__ __forceinline__ void add2(ull& d, ull a) {
    asm("add.rn.f32x2 %0, %0, %1;" : "+l"(d) : "l"(a));
}

// ---------------- zero stat buckets ------------------------------------------------
__global__ void k_zero_stats() {
    int n = NBUCK * NCH;
    for (int i = blockIdx.x * blockDim.x + threadIdx.x; i < n; i += gridDim.x * blockDim.x) {
        ((double*)g_sumB)[i] = 0.0;
        ((double*)g_sqB)[i]  = 0.0;
    }
}

// ---------------- pass 1: stats of h1 ---------------------------------------------
__global__ void k_stats1(const float* __restrict__ x,
                         const float* __restrict__ W1,
                         const float* __restrict__ b1, int V) {
    int N = V * PP;
    float lsum[C1], lsq[C1];
    #pragma unroll
    for (int u = 0; u < C1; u++) { lsum[u] = 0.f; lsq[u] = 0.f; }
    for (int r = blockIdx.x * blockDim.x + threadIdx.x; r < N; r += gridDim.x * blockDim.x) {
        float xv[CIN];
        #pragma unroll
        for (int c = 0; c < CIN; c++) xv[c] = x[(size_t)r * CIN + c];
        #pragma unroll
        for (int u = 0; u < C1; u++) {
            float h = b1[u];
            #pragma unroll
            for (int c = 0; c < CIN; c++) h = fmaf(xv[c], W1[c * C1 + u], h);
            lsum[u] += h; lsq[u] += h * h;
        }
    }
    __shared__ float ssum[C1], ssq[C1];
    if (threadIdx.x < C1) { ssum[threadIdx.x] = 0.f; ssq[threadIdx.x] = 0.f; }
    __syncthreads();
    #pragma unroll
    for (int u = 0; u < C1; u++) { atomicAdd(&ssum[u], lsum[u]); atomicAdd(&ssq[u], lsq[u]); }
    __syncthreads();
    if (threadIdx.x < C1) {
        int b = blockIdx.x & (NBUCK - 1);
        atomicAdd(&g_sumB[b][threadIdx.x], (double)ssum[threadIdx.x]);
        atomicAdd(&g_sqB [b][threadIdx.x], (double)ssq [threadIdx.x]);
    }
}

// ---------------- finalize BN params -----------------------------------------------
__global__ void k_finalize(const float* __restrict__ g, const float* __restrict__ be,
                           int off, int nc, double invN) {
    int u = threadIdx.x;
    if (u < nc) {
        double s = 0.0, q = 0.0;
        for (int b = 0; b < NBUCK; b++) { s += g_sumB[b][off + u]; q += g_sqB[b][off + u]; }
        double m   = s * invN;
        double var = q * invN - m * m;
        float  sc  = g[u] * rsqrtf((float)var + 1e-5f);
        g_scale[off + u] = sc;
        g_shift[off + u] = (float)((double)be[u] - m * (double)sc);
    }
}

// ---------------- pass 2: BN1+relu, max; HALVED h2 GEMM -> g_h2 -------------------
__global__ void __launch_bounds__(128) k_vfe1(const float* __restrict__ x,
                       const float* __restrict__ W1, const float* __restrict__ b1,
                       const float* __restrict__ W2, const float* __restrict__ b2, int V) {
    int v = blockIdx.x;
    if (v >= V) return;
    int t = threadIdx.x;

    __shared__ float  s_x[PP * CIN];
    __shared__ float  s_keep[PP + 1];
    __shared__ float  s_h1[PP * C1];
    __shared__ float  s_m1[C1];
    __shared__ float  s_C[C2];
    __shared__ float2 s_a1p[C1 * NP1];
    __shared__ float  s_w2[A1C * C2];
    __shared__ float  s_rs[4 * C2], s_rq[4 * C2];

    const float* xb = x + (size_t)v * (PP * CIN);
    for (int i = t; i < PP * CIN; i += 128) s_x[i] = xb[i];
    for (int i = t; i < A1C * C2; i += 128) s_w2[i] = W2[i];
    __syncthreads();

    if (t < PP) {
        float s = 0.f;
        #pragma unroll
        for (int c = 0; c < CIN; c++) s += s_x[t * CIN + c];
        float k = (s != 0.0f) ? 1.0f : 0.0f;
        s_keep[t] = k;
        g_keep[(size_t)v * PP + t] = k;
    }
    __syncthreads();

    for (int i = t; i < PP * C1; i += 128) {
        int p = i >> 4, u = i & 15;
        float h = b1[u];
        #pragma unroll
        for (int c = 0; c < CIN; c++) h = fmaf(s_x[p * CIN + c], W1[c * C1 + u], h);
        h = fmaf(h, g_scale[u], g_shift[u]);
        s_h1[i] = fmaxf(h, 0.0f);
    }
    __syncthreads();

    if (t < C1) {
        float m = s_h1[t];
        #pragma unroll 7
        for (int p = 1; p < PP; p++) m = fmaxf(m, s_h1[p * C1 + t]);
        s_m1[t] = m;
    }
    __syncthreads();

    for (int i = t; i < C1 * NP1; i += 128) {
        int k = i / NP1, pr = i % NP1;
        int p0 = 2 * pr, p1 = p0 + 1;
        float u0 = 0.f, u1 = 0.f;
        if (p0 < PP) u0 = s_h1[p0 * C1 + k] * s_keep[p0];
        if (p1 < PP) u1 = s_h1[p1 * C1 + k] * s_keep[p1];
        s_a1p[i] = make_float2(u0, u1);
    }
    if (t < C2) {
        float c = 0.f;
        #pragma unroll
        for (int k = 0; k < C1; k++) c = fmaf(s_m1[k], s_w2[(C1 + k) * C2 + t], c);
        s_C[t] = c;
    }
    __syncthreads();

    int lane = t & 31, pg = t >> 5;
    int og = lane * 2;
    ull acc[5][2];
    #pragma unroll
    for (int n = 0; n < 5; n++) { acc[n][0] = 0ULL; acc[n][1] = 0ULL; }

    #pragma unroll 4
    for (int k = 0; k < C1; k++) {
        float2 w = *(const float2*)&s_w2[k * C2 + og];
        ull w0 = pack2(w.x, w.x), w1 = pack2(w.y, w.y);
        const ull* ap = (const ull*)&s_a1p[k * NP1 + pg * 5];
        #pragma unroll
        for (int n = 0; n < 5; n++) {
            ull a = ap[n];
            fma2(acc[n][0], a, w0);
            fma2(acc[n][1], a, w1);
        }
    }

    float C0 = s_C[og], C1v = s_C[og + 1];
    float b0 = b2[og],  b1s = b2[og + 1];
    float ls0 = 0.f, lq0 = 0.f, ls1 = 0.f, lq1 = 0.f;
    float* h2g = g_h2 + (size_t)v * (PP * C2);
    #pragma unroll
    for (int n = 0; n < 5; n++) {
        int pr = pg * 5 + n;
        if (pr < 18) {
            int p0 = 2 * pr, p1 = p0 + 1;
            float2 r0 = unpack2(acc[n][0]);
            float2 r1 = unpack2(acc[n][1]);
            float k0 = s_keep[p0];
            float h00 = fmaf(k0, r0.x + C0,  b0);
            float h01 = fmaf(k0, r1.x + C1v, b1s);
            *(float2*)&h2g[p0 * C2 + og] = make_float2(h00, h01);
            ls0 += h00; lq0 += h00 * h00;
            ls1 += h01; lq1 += h01 * h01;
            if (p1 < PP) {
                float k1 = s_keep[p1];
                float h10 = fmaf(k1, r0.y + C0,  b0);
                float h11 = fmaf(k1, r1.y + C1v, b1s);
                *(float2*)&h2g[p1 * C2 + og] = make_float2(h10, h11);
                ls0 += h10; lq0 += h10 * h10;
                ls1 += h11; lq1 += h11 * h11;
            }
        }
    }
    s_rs[pg * C2 + og] = ls0; s_rs[pg * C2 + og + 1] = ls1;
    s_rq[pg * C2 + og] = lq0; s_rq[pg * C2 + og + 1] = lq1;
    __syncthreads();
    if (t < C2) {
        float S = s_rs[t] + s_rs[C2 + t] + s_rs[2 * C2 + t] + s_rs[3 * C2 + t];
        float Q = s_rq[t] + s_rq[C2 + t] + s_rq[2 * C2 + t] + s_rq[3 * C2 + t];
        int b = v & (NBUCK - 1);
        atomicAdd(&g_sumB[b][C1 + t], (double)S);
        atomicAdd(&g_sqB [b][C1 + t], (double)Q);
    }
}

// ---------------- pass 3: 4 groups x 128 threads; 8-output tile; reg stats --------
// phys permutation: true o = 8*ogi + e (ogi 0..15, e 0..7)
//   phys = (e>>2)*64 + 4*ogi + (e&3)
#define HB_S   68
#define G_HB   0           // 40*68 = 2720
#define G_KEEP 2720        // 40
#define G_MM   2760        // 1024: [8 wgrp][16 cgrp][8]
#define G_M2   3784        // 64
#define G_B    3848        // 128
#define G_RED  3976        // 4 warps * 16 ogi * 32 = 2048
#define G_SS   6024        // 128
#define G_SQ   6152        // 128
#define GRPSZ  6280
#define F_SC   16384
#define F_SH   16448
#define F_GRP  16512
#define SM2_BYTES ((F_GRP + NGRP * GRPSZ) * 4)

#define GBAR() asm volatile("bar.sync %0, %1;" :: "r"(gi + 1), "r"(GT) : "memory")

__global__ void __launch_bounds__(T2V, 1) k_vfe2(const float4* __restrict__ Wd4,
                                                 const float*  __restrict__ bd, int V) {
    extern __shared__ float sm2[];
    float* s_wd = sm2;                 // [128][128] phys-permuted
    float* s_sc = sm2 + F_SC;
    float* s_sh = sm2 + F_SH;

    int t = threadIdx.x;

    // ---- one-time staging: Wd phys-permuted ----
    for (int i = t; i < A2C * 32; i += T2V) {
        int k = i >> 5, c = i & 31;        // c: float4 col -> floats 4c..4c+3
        int ogi = c >> 1, half = c & 1;
        float4 wv = Wd4[i];
        *(float4*)(s_wd + k * A2C + half * 64 + 4 * ogi) = wv;
    }
    if (t < C2) { s_sc[t] = g_scale[C1 + t]; s_sh[t] = g_shift[C1 + t]; }

    int gi = t >> 7;                   // group 0..3 (warp-uniform)
    int lt = t & 127;

    float* buf    = sm2 + F_GRP + gi * GRPSZ + G_HB;
    float* s_keep = sm2 + F_GRP + gi * GRPSZ + G_KEEP;
    float* s_mm   = sm2 + F_GRP + gi * GRPSZ + G_MM;
    float* s_m2   = sm2 + F_GRP + gi * GRPSZ + G_M2;
    float* s_B    = sm2 + F_GRP + gi * GRPSZ + G_B;
    float* s_red  = sm2 + F_GRP + gi * GRPSZ + G_RED;
    float* s_Ss   = sm2 + F_GRP + gi * GRPSZ + G_SS;
    float* s_Sq   = sm2 + F_GRP + gi * GRPSZ + G_SQ;

    if (lt < 128) { s_Ss[lt] = 0.f; s_Sq[lt] = 0.f; }
    // zero hb pad rows 35..39 once (never clobbered)
    for (int j = lt; j < 5 * HB_S; j += GT) buf[35 * HB_S + j] = 0.f;
    __syncthreads();

    int ogi  = lt & 15;                // 8 outputs: o in [8*ogi, 8*ogi+8)
    int slot = lt >> 4;                // 0..7 -> rows slot+8j, j=0..4
    int wrp  = lt >> 5;                // 0..3
    int lane = lt & 31;

    for (int v = blockIdx.x * NGRP + gi; v < V; v += NSTREAM) {
        const float* keepg = g_keep + (size_t)v * PP;

        // ---- phase 1: load h2 + BN2 + relu + keep-fold -> hb; raw min/max ----
        {
            if (lt < 40) s_keep[lt] = (lt < PP) ? keepg[lt] : 0.f;
            float rmx[4], rmn[4];
            #pragma unroll
            for (int q = 0; q < 4; q++) { rmx[q] = -3.4e38f; rmn[q] = 3.4e38f; }
            const float4* h2g4 = (const float4*)(g_h2 + (size_t)v * (PP * C2));
            int c4 = (lt & 15) * 4;
            float4 scv = *(const float4*)(s_sc + c4);
            float4 shv = *(const float4*)(s_sh + c4);
            for (int i = lt; i < (PP * C2) / 4; i += GT) {
                float4 h = h2g4[i];
                int p = i >> 4;
                float kp = keepg[p];
                rmx[0] = fmaxf(rmx[0], h.x); rmn[0] = fminf(rmn[0], h.x);
                rmx[1] = fmaxf(rmx[1], h.y); rmn[1] = fminf(rmn[1], h.y);
                rmx[2] = fmaxf(rmx[2], h.z); rmn[2] = fminf(rmn[2], h.z);
                rmx[3] = fmaxf(rmx[3], h.w); rmn[3] = fminf(rmn[3], h.w);
                float4 o;
                o.x = fmaxf(fmaf(h.x, scv.x, shv.x), 0.f) * kp;
                o.y = fmaxf(fmaf(h.y, scv.y, shv.y), 0.f) * kp;
                o.z = fmaxf(fmaf(h.z, scv.z, shv.z), 0.f) * kp;
                o.w = fmaxf(fmaf(h.w, scv.w, shv.w), 0.f) * kp;
                *(float4*)(buf + p * HB_S + c4) = o;
            }
            float* mm = s_mm + (lt >> 4) * 128 + (lt & 15) * 8;
            #pragma unroll
            for (int q = 0; q < 4; q++) { mm[q] = rmx[q]; mm[4 + q] = rmn[q]; }
        }
        GBAR();

        // ---- phase 2: finalize m2 (max over p of relu(bn(h2)), unmasked) ----
        if (lt < C2) {
            int cg = lt >> 2, r = lt & 3;
            float MX = -3.4e38f, MN = 3.4e38f;
            #pragma unroll
            for (int w = 0; w < 8; w++) {
                MX = fmaxf(MX, s_mm[w * 128 + cg * 8 + r]);
                MN = fminf(MN, s_mm[w * 128 + cg * 8 + 4 + r]);
            }
            float sc = s_sc[lt];
            float sel = (sc >= 0.f) ? MX : MN;
            s_m2[lt] = fmaxf(fmaf(sel, sc, s_sh[lt]), 0.f);
        }
        GBAR();

        // ---- phase 3: B vector (scalar, 2 chains) then GEMM ----
        {
            float ba = 0.f, bb = 0.f;
            #pragma unroll 8
            for (int k = 0; k < 32; k++) {
                ba = fmaf(s_m2[k],      s_wd[(64 + k) * A2C + lt], ba);
                bb = fmaf(s_m2[k + 32], s_wd[(96 + k) * A2C + lt], bb);
            }
            s_B[lt] = ba + bb;
        }

        ull acc[5][4];
        #pragma unroll
        for (int j = 0; j < 5; j++)
            #pragma unroll
            for (int q = 0; q < 4; q++) acc[j][q] = 0ULL;

        const float* hbs = buf + slot * HB_S;
        #pragma unroll 2
        for (int k = 0; k < 64; k++) {
            const ulonglong2* wk = (const ulonglong2*)(s_wd + k * A2C);
            ulonglong2 wA = wk[ogi];          // phys 4*ogi..+3   (e 0..3)
            ulonglong2 wB = wk[16 + ogi];     // phys 64+4*ogi..  (e 4..7)
            #pragma unroll
            for (int j = 0; j < 5; j++) {
                float a = hbs[j * 8 * HB_S + k];
                ull ap = pack2(a, a);
                fma2(acc[j][0], ap, wA.x); fma2(acc[j][1], ap, wA.y);
                fma2(acc[j][2], ap, wB.x); fma2(acc[j][3], ap, wB.y);
            }
        }
        GBAR();   // hb reads + B writes complete

        // ---- phase 4: epilogue + register stats + slot-pair shfl reduce ----
        {
            float kp[5]; bool val[5];
            #pragma unroll
            for (int j = 0; j < 5; j++) {
                int p = slot + 8 * j;
                val[j] = (p < PP);
                kp[j]  = val[j] ? s_keep[p] : 0.f;
            }
            #pragma unroll
            for (int q = 0; q < 4; q++) {
                int bi = (q & 1) + 2 * ogi + (q >> 1) * 32;
                ull Bq  = ((const ull*)s_B)[bi];
                ull bdq = ((const ull*)bd)[4 * ogi + q];
                float S0 = 0.f, Q0 = 0.f, S1 = 0.f, Q1 = 0.f;
                float MX0 = -3.4e38f, MN0 = 3.4e38f, MX1 = -3.4e38f, MN1 = 3.4e38f;
                #pragma unroll
                for (int j = 0; j < 5; j++) {
                    ull kpp = pack2(kp[j], kp[j]);
                    fma2(acc[j][q], Bq, kpp); add2(acc[j][q], bdq);
                    if (val[j]) {
                        float2 r = unpack2(acc[j][q]);
                        S0 += r.x; Q0 = fmaf(r.x, r.x, Q0);
                        MX0 = fmaxf(MX0, r.x); MN0 = fminf(MN0, r.x);
                        S1 += r.y; Q1 = fmaf(r.y, r.y, Q1);
                        MX1 = fmaxf(MX1, r.y); MN1 = fminf(MN1, r.y);
                    }
                }
                // combine slot pair (lane ^ 16 has same ogi, adjacent slot)
                S0 += __shfl_xor_sync(0xffffffffu, S0, 16);
                Q0 += __shfl_xor_sync(0xffffffffu, Q0, 16);
                MX0 = fmaxf(MX0, __shfl_xor_sync(0xffffffffu, MX0, 16));
                MN0 = fminf(MN0, __shfl_xor_sync(0xffffffffu, MN0, 16));
                S1 += __shfl_xor_sync(0xffffffffu, S1, 16);
                Q1 += __shfl_xor_sync(0xffffffffu, Q1, 16);
                MX1 = fmaxf(MX1, __shfl_xor_sync(0xffffffffu, MX1, 16));
                MN1 = fminf(MN1, __shfl_xor_sync(0xffffffffu, MN1, 16));
                if (lane < 16) {
                    float* rd = s_red + wrp * 512 + ogi * 32 + q * 8;
                    rd[0] = S0; rd[1] = Q0; rd[2] = MX0; rd[3] = MN0;
                    rd[4] = S1; rd[5] = Q1; rd[6] = MX1; rd[7] = MN1;
                }
            }
        }
        GBAR();

        // ---- phase 5: combine 4 warps; running sums; store mx/mn (coalesced) ----
        {
            int o = lt;                    // true channel
            int cogi = o >> 3, e = o & 7, cq = e >> 1, h = e & 1;
            const float* rd = s_red + cogi * 32 + cq * 8 + h * 4;
            float S = 0.f, Q = 0.f, MX = -3.4e38f, MN = 3.4e38f;
            #pragma unroll
            for (int w = 0; w < 4; w++) {
                S += rd[w * 512 + 0];
                Q += rd[w * 512 + 1];
                MX = fmaxf(MX, rd[w * 512 + 2]);
                MN = fminf(MN, rd[w * 512 + 3]);
            }
            s_Ss[o] += S; s_Sq[o] += Q;
            g_max3[(size_t)v * C3 + o] = MX;
            g_min3[(size_t)v * C3 + o] = MN;
        }
        // no barrier needed: next phase 1 touches hb/keep/mm only, and the
        // phase-1 GBAR orders those against this iteration's readers.
    }

    // ---- end: flush running stats once per group (own writes; no race) ----
    GBAR();
    {
        int b = (blockIdx.x * NGRP + gi) & (NBUCK - 1);
        atomicAdd(&g_sumB[b][C1 + C2 + lt], (double)s_Ss[lt]);
        atomicAdd(&g_sqB [b][C1 + C2 + lt], (double)s_Sq[lt]);
    }
}

// ---------------- pass 4: BN3 + relu + max (via max/min) + scatter-add ------------
__global__ void k_scatter(const int* __restrict__ coord, float* __restrict__ out, int V) {
    int v = blockIdx.x;
    if (v >= V) return;
    int u = threadIdx.x;
    float sc = g_scale[C1 + C2 + u];
    float sh = g_shift[C1 + C2 + u];
    float h  = (sc >= 0.0f) ? g_max3[(size_t)v * C3 + u] : g_min3[(size_t)v * C3 + u];
    float val = fmaxf(fmaf(h, sc, sh), 0.0f);
    int cz = coord[v * 3 + 0];
    int cy = coord[v * 3 + 1];
    int cx = coord[v * 3 + 2];
    size_t off = (size_t)u * (DD * HH * WWG) + (size_t)cz * (HH * WWG) + (size_t)cy * WWG + cx;
    atomicAdd(out + off, val);
}

// ---------------- launch -----------------------------------------------------------
extern "C" void kernel_launch(void* const* d_in, const int* in_sizes, int n_in,
                              void* d_out, int out_size) {
    const float* x     = (const float*)d_in[0];
    const int*   coord = (const int*)  d_in[1];
    const float* W1 = (const float*)d_in[2];
    const float* b1 = (const float*)d_in[3];
    const float* g1 = (const float*)d_in[4];
    const float* be1= (const float*)d_in[5];
    const float* W2 = (const float*)d_in[6];
    const float* b2 = (const float*)d_in[7];
    const float* g2 = (const float*)d_in[8];
    const float* be2= (const float*)d_in[9];
    const float* Wd = (const float*)d_in[10];
    const float* bd = (const float*)d_in[11];
    const float* gd = (const float*)d_in[12];
    const float* bed= (const float*)d_in[13];

    int V = in_sizes[1] / 3;
    if (V > VMAX) V = VMAX;
    double invN = 1.0 / ((double)V * PP);

    cudaFuncSetAttribute(k_vfe2, cudaFuncAttributeMaxDynamicSharedMemorySize, SM2_BYTES);

    cudaMemsetAsync(d_out, 0, (size_t)out_size * sizeof(float), 0);
    k_zero_stats<<<32, 256>>>();
    k_stats1<<<592, 256>>>(x, W1, b1, V);
    k_finalize<<<1, 256>>>(g1, be1, 0, C1, invN);
    k_vfe1<<<V, 128>>>(x, W1, b1, W2, b2, V);
    k_finalize<<<1, 256>>>(g2, be2, C1, C2, invN);
    k_vfe2<<<GRID2, T2V, SM2_BYTES>>>((const float4*)Wd, bd, V);
    k_finalize<<<1, 256>>>(gd, bed, C1 + C2, C3, invN);
    k_scatter<<<V, 128>>>(coord, (float*)d_out, V);
}

// round 15
// speedup vs baseline: 1.0295x; 1.0295x over previous
#include <cuda_runtime.h>

#define PP    35
#define CIN   7
#define C1    16
#define A1C   32
#define C2    64
#define A2C   128
#define C3    128
#define DD    10
#define HH    200
#define WWG   176
#define VMAX  20000
#define NBUCK 64
#define NCH   (C1 + C2 + C3)   // 208
#define NP1   20
#define NGRP  4
#define GT    128
#define T2V   (NGRP * GT)      // 512
#define GRID2 148
#define NSTREAM (GRID2 * NGRP) // 592

typedef unsigned long long ull;
typedef unsigned int uint32;

// ---------------- scratch ---------------------------------------------------------
__device__ float  g_h2[(size_t)VMAX * PP * C2];
__device__ float  g_keep[(size_t)VMAX * PP];
__device__ float  g_max3[(size_t)VMAX * C3];
__device__ float  g_min3[(size_t)VMAX * C3];
__device__ double g_sumB [NBUCK][NCH];
__device__ double g_sqB  [NBUCK][NCH];
__device__ float  g_scale[NCH];
__device__ float  g_shift[NCH];
__device__ unsigned short g_wbhi[A2C * A2C];   // Wd^T bf16 hi: [o][k]
__device__ unsigned short g_wblo[A2C * A2C];   // Wd^T bf16 lo

// ---------------- f32x2 helpers (vfe1) ----------------------------------------------
__device__ __forceinline__ ull pack2(float lo, float hi) {
    ull r;
    asm("mov.b64 %0, {%1, %2};" : "=l"(r) : "f"(lo), "f"(hi));
    return r;
}
__device__ __forceinline__ float2 unpack2(ull v) {
    float2 r;
    asm("mov.b64 {%0, %1}, %2;" : "=f"(r.x), "=f"(r.y) : "l"(v));
    return r;
}
__device__ __forceinline__ void fma2(ull& d, ull a, ull b) {
    asm("fma.rn.f32x2 %0, %1, %2, %0;" : "+l"(d) : "l"(a), "l"(b));
}

// ---------------- bf16 helpers -------------------------------------------------------
__device__ __forceinline__ unsigned short f2bf(float w) {
    unsigned short r;
    asm("cvt.rn.bf16.f32 %0, %1;" : "=h"(r) : "f"(w));
    return r;
}
__device__ __forceinline__ uint32 bf2pack(float e, float o) {   // lo16 = e, hi16 = o
    uint32 r;
    asm("cvt.rn.bf16x2.f32 %0, %1, %2;" : "=r"(r) : "f"(o), "f"(e));
    return r;
}
__device__ __forceinline__ uint32 smem_u32(const void* p) {
    uint32 a;
    asm("{ .reg .u64 t; cvta.to.shared.u64 t, %1; cvt.u32.u64 %0, t; }" : "=r"(a) : "l"(p));
    return a;
}

// ---------------- mma.sync helpers ---------------------------------------------------
#define LDSM4(r, a) asm volatile( \
    "ldmatrix.sync.aligned.m8n8.x4.shared.b16 {%0,%1,%2,%3}, [%4];" \
    : "=r"((r)[0]), "=r"((r)[1]), "=r"((r)[2]), "=r"((r)[3]) : "r"(a))

#define MMA16(c, a, b0, b1) asm volatile( \
    "mma.sync.aligned.m16n8k16.row.col.f32.bf16.bf16.f32 " \
    "{%0,%1,%2,%3}, {%4,%5,%6,%7}, {%8,%9}, {%0,%1,%2,%3};" \
    : "+f"((c)[0]), "+f"((c)[1]), "+f"((c)[2]), "+f"((c)[3]) \
    : "r"((a)[0]), "r"((a)[1]), "r"((a)[2]), "r"((a)[3]), "r"(b0), "r"(b1))

// ---------------- zero stat buckets --------------------------------------------------
__global__ void k_zero_stats() {
    int n = NBUCK * NCH;
    for (int i = blockIdx.x * blockDim.x + threadIdx.x; i < n; i += gridDim.x * blockDim.x) {
        ((double*)g_sumB)[i] = 0.0;
        ((double*)g_sqB)[i]  = 0.0;
    }
}

// ---------------- prep: Wd^T -> bf16 hi/lo [o][k] -----------------------------------
__global__ void k_prepwd(const float* __restrict__ Wd) {
    int idx = blockIdx.x * 256 + threadIdx.x;
    if (idx < A2C * A2C) {
        int k = idx >> 7, o = idx & 127;
        float w = Wd[idx];                      // Wd[k][o]
        unsigned short h = f2bf(w);
        float hf = __uint_as_float((uint32)h << 16);
        unsigned short l = f2bf(w - hf);
        g_wbhi[o * A2C + k] = h;
        g_wblo[o * A2C + k] = l;
    }
}

// ---------------- pass 1: stats of h1 ------------------------------------------------
__global__ void k_stats1(const float* __restrict__ x,
                         const float* __restrict__ W1,
                         const float* __restrict__ b1, int V) {
    int N = V * PP;
    float lsum[C1], lsq[C1];
    #pragma unroll
    for (int u = 0; u < C1; u++) { lsum[u] = 0.f; lsq[u] = 0.f; }
    for (int r = blockIdx.x * blockDim.x + threadIdx.x; r < N; r += gridDim.x * blockDim.x) {
        float xv[CIN];
        #pragma unroll
        for (int c = 0; c < CIN; c++) xv[c] = x[(size_t)r * CIN + c];
        #pragma unroll
        for (int u = 0; u < C1; u++) {
            float h = b1[u];
            #pragma unroll
            for (int c = 0; c < CIN; c++) h = fmaf(xv[c], W1[c * C1 + u], h);
            lsum[u] += h; lsq[u] += h * h;
        }
    }
    __shared__ float ssum[C1], ssq[C1];
    if (threadIdx.x < C1) { ssum[threadIdx.x] = 0.f; ssq[threadIdx.x] = 0.f; }
    __syncthreads();
    #pragma unroll
    for (int u = 0; u < C1; u++) { atomicAdd(&ssum[u], lsum[u]); atomicAdd(&ssq[u], lsq[u]); }
    __syncthreads();
    if (threadIdx.x < C1) {
        int b = blockIdx.x & (NBUCK - 1);
        atomicAdd(&g_sumB[b][threadIdx.x], (double)ssum[threadIdx.x]);
        atomicAdd(&g_sqB [b][threadIdx.x], (double)ssq [threadIdx.x]);
    }
}

// ---------------- finalize BN params --------------------------------------------------
__global__ void k_finalize(const float* __restrict__ g, const float* __restrict__ be,
                           int off, int nc, double invN) {
    int u = threadIdx.x;
    if (u < nc) {
        double s = 0.0, q = 0.0;
        for (int b = 0; b < NBUCK; b++) { s += g_sumB[b][off + u]; q += g_sqB[b][off + u]; }
        double m   = s * invN;
        double var = q * invN - m * m;
        float  sc  = g[u] * rsqrtf((float)var + 1e-5f);
        g_scale[off + u] = sc;
        g_shift[off + u] = (float)((double)be[u] - m * (double)sc);
    }
}

// ---------------- pass 2: BN1+relu, max; HALVED h2 GEMM -> g_h2 ----------------------
__global__ void __launch_bounds__(128) k_vfe1(const float* __restrict__ x,
                       const float* __restrict__ W1, const float* __restrict__ b1,
                       const float* __restrict__ W2, const float* __restrict__ b2, int V) {
    int v = blockIdx.x;
    if (v >= V) return;
    int t = threadIdx.x;

    __shared__ float  s_x[PP * CIN];
    __shared__ float  s_keep[PP + 1];
    __shared__ float  s_h1[PP * C1];
    __shared__ float  s_m1[C1];
    __shared__ float  s_C[C2];
    __shared__ float2 s_a1p[C1 * NP1];
    __shared__ float  s_w2[A1C * C2];
    __shared__ float  s_rs[4 * C2], s_rq[4 * C2];

    const float* xb = x + (size_t)v * (PP * CIN);
    for (int i = t; i < PP * CIN; i += 128) s_x[i] = xb[i];
    for (int i = t; i < A1C * C2; i += 128) s_w2[i] = W2[i];
    __syncthreads();

    if (t < PP) {
        float s = 0.f;
        #pragma unroll
        for (int c = 0; c < CIN; c++) s += s_x[t * CIN + c];
        float k = (s != 0.0f) ? 1.0f : 0.0f;
        s_keep[t] = k;
        g_keep[(size_t)v * PP + t] = k;
    }
    __syncthreads();

    for (int i = t; i < PP * C1; i += 128) {
        int p = i >> 4, u = i & 15;
        float h = b1[u];
        #pragma unroll
        for (int c = 0; c < CIN; c++) h = fmaf(s_x[p * CIN + c], W1[c * C1 + u], h);
        h = fmaf(h, g_scale[u], g_shift[u]);
        s_h1[i] = fmaxf(h, 0.0f);
    }
    __syncthreads();

    if (t < C1) {
        float m = s_h1[t];
        #pragma unroll 7
        for (int p = 1; p < PP; p++) m = fmaxf(m, s_h1[p * C1 + t]);
        s_m1[t] = m;
    }
    __syncthreads();

    for (int i = t; i < C1 * NP1; i += 128) {
        int k = i / NP1, pr = i % NP1;
        int p0 = 2 * pr, p1 = p0 + 1;
        float u0 = 0.f, u1 = 0.f;
        if (p0 < PP) u0 = s_h1[p0 * C1 + k] * s_keep[p0];
        if (p1 < PP) u1 = s_h1[p1 * C1 + k] * s_keep[p1];
        s_a1p[i] = make_float2(u0, u1);
    }
    if (t < C2) {
        float c = 0.f;
        #pragma unroll
        for (int k = 0; k < C1; k++) c = fmaf(s_m1[k], s_w2[(C1 + k) * C2 + t], c);
        s_C[t] = c;
    }
    __syncthreads();

    int lane = t & 31, pg = t >> 5;
    int og = lane * 2;
    ull acc[5][2];
    #pragma unroll
    for (int n = 0; n < 5; n++) { acc[n][0] = 0ULL; acc[n][1] = 0ULL; }

    #pragma unroll 4
    for (int k = 0; k < C1; k++) {
        float2 w = *(const float2*)&s_w2[k * C2 + og];
        ull w0 = pack2(w.x, w.x), w1 = pack2(w.y, w.y);
        const ull* ap = (const ull*)&s_a1p[k * NP1 + pg * 5];
        #pragma unroll
        for (int n = 0; n < 5; n++) {
            ull a = ap[n];
            fma2(acc[n][0], a, w0);
            fma2(acc[n][1], a, w1);
        }
    }

    float C0 = s_C[og], C1v = s_C[og + 1];
    float b0 = b2[og],  b1s = b2[og + 1];
    float ls0 = 0.f, lq0 = 0.f, ls1 = 0.f, lq1 = 0.f;
    float* h2g = g_h2 + (size_t)v * (PP * C2);
    #pragma unroll
    for (int n = 0; n < 5; n++) {
        int pr = pg * 5 + n;
        if (pr < 18) {
            int p0 = 2 * pr, p1 = p0 + 1;
            float2 r0 = unpack2(acc[n][0]);
            float2 r1 = unpack2(acc[n][1]);
            float k0 = s_keep[p0];
            float h00 = fmaf(k0, r0.x + C0,  b0);
            float h01 = fmaf(k0, r1.x + C1v, b1s);
            *(float2*)&h2g[p0 * C2 + og] = make_float2(h00, h01);
            ls0 += h00; lq0 += h00 * h00;
            ls1 += h01; lq1 += h01 * h01;
            if (p1 < PP) {
                float k1 = s_keep[p1];
                float h10 = fmaf(k1, r0.y + C0,  b0);
                float h11 = fmaf(k1, r1.y + C1v, b1s);
                *(float2*)&h2g[p1 * C2 + og] = make_float2(h10, h11);
                ls0 += h10; lq0 += h10 * h10;
                ls1 += h11; lq1 += h11 * h11;
            }
        }
    }
    s_rs[pg * C2 + og] = ls0; s_rs[pg * C2 + og + 1] = ls1;
    s_rq[pg * C2 + og] = lq0; s_rq[pg * C2 + og + 1] = lq1;
    __syncthreads();
    if (t < C2) {
        float S = s_rs[t] + s_rs[C2 + t] + s_rs[2 * C2 + t] + s_rs[3 * C2 + t];
        float Q = s_rq[t] + s_rq[C2 + t] + s_rq[2 * C2 + t] + s_rq[3 * C2 + t];
        int b = v & (NBUCK - 1);
        atomicAdd(&g_sumB[b][C1 + t], (double)S);
        atomicAdd(&g_sqB [b][C1 + t], (double)Q);
    }
}

// ---------------- pass 3: mma.sync bf16 hi/lo GEMM; register epilogue ----------------
// A: [48][136] bf16 (rows 35..47 zero pad); B: Wd^T [128][136] bf16; both hi+lo.
#define AST   136               // shorts per A/B row (272 B: ldmatrix conflict-free)
#define O_BHI 0                 // 8704 floats (128*136 shorts / 2)
#define O_BLO 8704
#define O_SC  17408
#define O_SH  17472
#define O_BD  17536
#define O_GRP 17664
#define GA_HI 0                 // 3264 floats (48*136/2)
#define GA_LO 3264
#define GMM   6528              // 1024 (raw max/min interleaved)
#define GM2   7552              // 64
#define GKEEP 7616              // 48
#define GSS   7664              // 128
#define GSQ   7792              // 128
#define GRPF  7920
#define SM3_BYTES ((O_GRP + NGRP * GRPF) * 4)

#define GBAR() asm volatile("bar.sync %0, %1;" :: "r"(gi + 1), "r"(GT) : "memory")

__global__ void __launch_bounds__(T2V, 1) k_vfe2(const float* __restrict__ bd, int V) {
    extern __shared__ float sm3[];
    int t = threadIdx.x;

    float* s_sc = sm3 + O_SC;
    float* s_sh = sm3 + O_SH;
    float* s_bd = sm3 + O_BD;

    // ---- one-time staging: B hi/lo (row o stride 136 shorts) ----
    {
        uint32* dBh = (uint32*)(sm3 + O_BHI);
        uint32* dBl = (uint32*)(sm3 + O_BLO);
        const uint32* sBh = (const uint32*)g_wbhi;
        const uint32* sBl = (const uint32*)g_wblo;
        for (int i = t; i < A2C * 64; i += T2V) {
            int o = i >> 6, k2 = i & 63;
            dBh[o * 68 + k2] = sBh[i];
            dBl[o * 68 + k2] = sBl[i];
        }
    }
    if (t < C2)  { s_sc[t] = g_scale[C1 + t]; s_sh[t] = g_shift[C1 + t]; }
    if (t < 128) s_bd[t] = bd[t];

    int gi = t >> 7;               // group 0..3
    int lt = t & 127;

    float* grp    = sm3 + O_GRP + gi * GRPF;
    uint32* aHi32 = (uint32*)(grp + GA_HI);
    uint32* aLo32 = (uint32*)(grp + GA_LO);
    float* s_mm   = grp + GMM;
    float* s_m2   = grp + GM2;
    float* s_keep = grp + GKEEP;
    float* s_Ss   = grp + GSS;
    float* s_Sq   = grp + GSQ;

    if (lt < 128) { s_Ss[lt] = 0.f; s_Sq[lt] = 0.f; }
    // zero pad rows 35..47 of A (hi+lo), once
    for (int i = lt; i < 13 * 68; i += GT) {
        int row = 35 + i / 68, cu = i % 68;
        aHi32[row * 68 + cu] = 0u;
        aLo32[row * 68 + cu] = 0u;
    }
    __syncthreads();

    uint32 aHiB = smem_u32(grp + GA_HI);
    uint32 aLoB = smem_u32(grp + GA_LO);
    uint32 bHiB = smem_u32(sm3 + O_BHI);
    uint32 bLoB = smem_u32(sm3 + O_BLO);

    int wrp = lt >> 5, lane = lt & 31;
    int n0 = wrp * 32;
    int lrow = lane & 15, lcolA = (lane >> 4) << 3;
    int q8 = lane >> 3, r8 = lane & 7;
    uint32 aOff = (uint32)(lrow * AST + lcolA) * 2u;
    uint32 bOff = (uint32)((n0 + ((q8 >> 1) << 3) + r8) * AST + ((q8 & 1) << 3)) * 2u;

    int c4 = (lt & 15) * 4;
    float4 scv = *(const float4*)(s_sc + c4);
    float4 shv = *(const float4*)(s_sh + c4);

    for (int v = blockIdx.x * NGRP + gi; v < V; v += NSTREAM) {
        const float* keepg = g_keep + (size_t)v * PP;

        // ---- phase 1: h2 load + BN2+relu+keep -> A lower (bf16 hi/lo); raw min/max --
        if (lt < 48) s_keep[lt] = (lt < PP) ? keepg[lt] : 0.f;
        {
            float rmx[4], rmn[4];
            #pragma unroll
            for (int e = 0; e < 4; e++) { rmx[e] = -3.4e38f; rmn[e] = 3.4e38f; }
            const float4* h2g4 = (const float4*)(g_h2 + (size_t)v * (PP * C2));
            for (int i = lt; i < 16 * PP; i += GT) {
                float4 h = h2g4[i];
                int row = i >> 4;
                float kp = keepg[row];
                rmx[0] = fmaxf(rmx[0], h.x); rmn[0] = fminf(rmn[0], h.x);
                rmx[1] = fmaxf(rmx[1], h.y); rmn[1] = fminf(rmn[1], h.y);
                rmx[2] = fmaxf(rmx[2], h.z); rmn[2] = fminf(rmn[2], h.z);
                rmx[3] = fmaxf(rmx[3], h.w); rmn[3] = fminf(rmn[3], h.w);
                float ax = fmaxf(fmaf(h.x, scv.x, shv.x), 0.f) * kp;
                float ay = fmaxf(fmaf(h.y, scv.y, shv.y), 0.f) * kp;
                float az = fmaxf(fmaf(h.z, scv.z, shv.z), 0.f) * kp;
                float aw = fmaxf(fmaf(h.w, scv.w, shv.w), 0.f) * kp;
                uint32 hi01 = bf2pack(ax, ay);
                uint32 hi23 = bf2pack(az, aw);
                float rx = ax - __uint_as_float(hi01 << 16);
                float ry = ay - __uint_as_float(hi01 & 0xffff0000u);
                float rz = az - __uint_as_float(hi23 << 16);
                float rw = aw - __uint_as_float(hi23 & 0xffff0000u);
                uint32 lo01 = bf2pack(rx, ry);
                uint32 lo23 = bf2pack(rz, rw);
                int u32i = row * 68 + (i & 15) * 2;
                aHi32[u32i] = hi01; aHi32[u32i + 1] = hi23;
                aLo32[u32i] = lo01; aLo32[u32i + 1] = lo23;
            }
            float* mm = s_mm + (lt >> 4) * 128 + (lt & 15) * 8;
            #pragma unroll
            for (int e = 0; e < 4; e++) { mm[e] = rmx[e]; mm[4 + e] = rmn[e]; }
        }
        GBAR();

        // ---- phase 2: m2 finalize ----
        if (lt < C2) {
            int cg = lt >> 2, r = lt & 3;
            float MX = -3.4e38f, MN = 3.4e38f;
            #pragma unroll
            for (int w = 0; w < 8; w++) {
                MX = fmaxf(MX, s_mm[w * 128 + cg * 8 + r]);
                MN = fminf(MN, s_mm[w * 128 + cg * 8 + 4 + r]);
            }
            float sc = s_sc[lt];
            float sel = (sc >= 0.f) ? MX : MN;
            s_m2[lt] = fmaxf(fmaf(sel, sc, s_sh[lt]), 0.f);
        }
        GBAR();

        // ---- phase 3: A upper = keep[row] * m2 (bf16 hi/lo) ----
        for (int idx = lt; idx < PP * 32; idx += GT) {
            int row = idx >> 5, c2 = idx & 31;
            float kp = s_keep[row];
            float a0 = kp * s_m2[2 * c2];
            float a1 = kp * s_m2[2 * c2 + 1];
            uint32 hi = bf2pack(a0, a1);
            float r0 = a0 - __uint_as_float(hi << 16);
            float r1 = a1 - __uint_as_float(hi & 0xffff0000u);
            uint32 lo = bf2pack(r0, r1);
            int u32i = row * 68 + 32 + c2;
            aHi32[u32i] = hi;
            aLo32[u32i] = lo;
        }
        GBAR();

        // ---- phase 4: GEMM via mma.sync (3 passes: HH, HL, LH) ----
        float acc[3][4][4];
        #pragma unroll
        for (int mt = 0; mt < 3; mt++)
            #pragma unroll
            for (int nt = 0; nt < 4; nt++)
                #pragma unroll
                for (int e = 0; e < 4; e++) acc[mt][nt][e] = 0.f;

        #pragma unroll
        for (int k0 = 0; k0 < 128; k0 += 16) {
            uint32 ah[3][4], al[3][4], bh[2][4], bl[2][4];
            #pragma unroll
            for (int mt = 0; mt < 3; mt++) {
                uint32 off = aOff + (uint32)(mt * 16 * AST + k0) * 2u;
                LDSM4(ah[mt], aHiB + off);
                LDSM4(al[mt], aLoB + off);
            }
            #pragma unroll
            for (int nh = 0; nh < 2; nh++) {
                uint32 off = bOff + (uint32)(nh * 16 * AST + k0) * 2u;
                LDSM4(bh[nh], bHiB + off);
                LDSM4(bl[nh], bLoB + off);
            }
            #pragma unroll
            for (int mt = 0; mt < 3; mt++) {
                #pragma unroll
                for (int nt = 0; nt < 4; nt++) {
                    const uint32* bhp = bh[nt >> 1];
                    const uint32* blp = bl[nt >> 1];
                    int pe = (nt & 1) * 2;
                    MMA16(acc[mt][nt], ah[mt], bhp[pe], bhp[pe + 1]);
                    MMA16(acc[mt][nt], ah[mt], blp[pe], blp[pe + 1]);
                    MMA16(acc[mt][nt], al[mt], bhp[pe], bhp[pe + 1]);
                }
            }
        }

        // ---- phase 5: register epilogue (+bd), masked stats, shfl reduce ----
        {
            int l4 = lane >> 2;
            bool v2 = (l4 < 3);     // mt2 row 32+l4 valid (<35)
            #pragma unroll
            for (int nt = 0; nt < 4; nt++) {
                #pragma unroll
                for (int e = 0; e < 2; e++) {
                    int c = n0 + nt * 8 + 2 * (lane & 3) + e;
                    float bdv = s_bd[c];
                    float h0 = acc[0][nt][e]     + bdv;
                    float h1 = acc[0][nt][e + 2] + bdv;
                    float h2 = acc[1][nt][e]     + bdv;
                    float h3 = acc[1][nt][e + 2] + bdv;
                    float S = h0 + h1 + h2 + h3;
                    float Q = fmaf(h0, h0, fmaf(h1, h1, fmaf(h2, h2, h3 * h3)));
                    float MX = fmaxf(fmaxf(h0, h1), fmaxf(h2, h3));
                    float MN = fminf(fminf(h0, h1), fminf(h2, h3));
                    if (v2) {
                        float h4 = acc[2][nt][e] + bdv;
                        S += h4; Q = fmaf(h4, h4, Q);
                        MX = fmaxf(MX, h4); MN = fminf(MN, h4);
                    }
                    #pragma unroll
                    for (int d = 4; d <= 16; d <<= 1) {
                        S += __shfl_xor_sync(0xffffffffu, S, d);
                        Q += __shfl_xor_sync(0xffffffffu, Q, d);
                        MX = fmaxf(MX, __shfl_xor_sync(0xffffffffu, MX, d));
                        MN = fminf(MN, __shfl_xor_sync(0xffffffffu, MN, d));
                    }
                    if (l4 == 0) {
                        g_max3[(size_t)v * C3 + c] = MX;
                        g_min3[(size_t)v * C3 + c] = MN;
                        s_Ss[c] += S;
                        s_Sq[c] += Q;
                    }
                }
            }
        }
        GBAR();   // A reads done before next iteration overwrites
    }

    // ---- flush running stats once per group ----
    GBAR();
    {
        int b = (blockIdx.x * NGRP + gi) & (NBUCK - 1);
        atomicAdd(&g_sumB[b][C1 + C2 + lt], (double)s_Ss[lt]);
        atomicAdd(&g_sqB [b][C1 + C2 + lt], (double)s_Sq[lt]);
    }
}

// ---------------- pass 4: BN3 + relu + max (via max/min) + scatter-add ---------------
__global__ void k_scatter(const int* __restrict__ coord, float* __restrict__ out, int V) {
    int v = blockIdx.x;
    if (v >= V) return;
    int u = threadIdx.x;
    float sc = g_scale[C1 + C2 + u];
    float sh = g_shift[C1 + C2 + u];
    float h  = (sc >= 0.0f) ? g_max3[(size_t)v * C3 + u] : g_min3[(size_t)v * C3 + u];
    float val = fmaxf(fmaf(h, sc, sh), 0.0f);
    int cz = coord[v * 3 + 0];
    int cy = coord[v * 3 + 1];
    int cx = coord[v * 3 + 2];
    size_t off = (size_t)u * (DD * HH * WWG) + (size_t)cz * (HH * WWG) + (size_t)cy * WWG + cx;
    atomicAdd(out + off, val);
}

// ---------------- launch ---------------------------------------------------------------
extern "C" void kernel_launch(void* const* d_in, const int* in_sizes, int n_in,
                              void* d_out, int out_size) {
    const float* x     = (const float*)d_in[0];
    const int*   coord = (const int*)  d_in[1];
    const float* W1 = (const float*)d_in[2];
    const float* b1 = (const float*)d_in[3];
    const float* g1 = (const float*)d_in[4];
    const float* be1= (const float*)d_in[5];
    const float* W2 = (const float*)d_in[6];
    const float* b2 = (const float*)d_in[7];
    const float* g2 = (const float*)d_in[8];
    const float* be2= (const float*)d_in[9];
    const float* Wd = (const float*)d_in[10];
    const float* bd = (const float*)d_in[11];
    const float* gd = (const float*)d_in[12];
    const float* bed= (const float*)d_in[13];

    int V = in_sizes[1] / 3;
    if (V > VMAX) V = VMAX;
    double invN = 1.0 / ((double)V * PP);

    cudaFuncSetAttribute(k_vfe2, cudaFuncAttributeMaxDynamicSharedMemorySize, SM3_BYTES);

    cudaMemsetAsync(d_out, 0, (size_t)out_size * sizeof(float), 0);
    k_zero_stats<<<32, 256>>>();
    k_prepwd<<<64, 256>>>(Wd);
    k_stats1<<<592, 256>>>(x, W1, b1, V);
    k_finalize<<<1, 256>>>(g1, be1, 0, C1, invN);
    k_vfe1<<<V, 128>>>(x, W1, b1, W2, b2, V);
    k_finalize<<<1, 256>>>(g2, be2, C1, C2, invN);
    k_vfe2<<<GRID2, T2V, SM3_BYTES>>>(bd, V);
    k_finalize<<<1, 256>>>(gd, bed, C1 + C2, C3, invN);
    k_scatter<<<V, 128>>>(coord, (float*)d_out, V);
}

// round 17
// speedup vs baseline: 1.1620x; 1.1287x over previous
#include <cuda_runtime.h>

#define PP    35
#define CIN   7
#define C1    16
#define A1C   32
#define C2    64
#define A2C   128
#define C3    128
#define DD    10
#define HH    200
#define WWG   176
#define VMAX  20000
#define NBUCK 64
#define NCH   (C1 + C2 + C3)   // 208
#define NP1   20
#define NGRP  4
#define GT    128
#define T2V   (NGRP * GT)      // 512
#define GRID2 148
#define NSTREAM (GRID2 * NGRP) // 592

typedef unsigned long long ull;
typedef unsigned int uint32;

// ---------------- scratch ---------------------------------------------------------
__device__ float  g_h2[(size_t)VMAX * PP * C2];
__device__ float  g_keep[(size_t)VMAX * PP];
__device__ float  g_max3[(size_t)VMAX * C3];
__device__ float  g_min3[(size_t)VMAX * C3];
__device__ double g_sumB [NBUCK][NCH];
__device__ double g_sqB  [NBUCK][NCH];
__device__ float  g_scale[NCH];
__device__ float  g_shift[NCH];
__device__ unsigned short g_wbhi[A2C * A2C];   // Wd^T bf16 hi: [o][k]
__device__ unsigned short g_wblo[A2C * A2C];   // Wd^T bf16 lo

// ---------------- f32x2 helpers (vfe1) ----------------------------------------------
__device__ __forceinline__ ull pack2(float lo, float hi) {
    ull r;
    asm("mov.b64 %0, {%1, %2};" : "=l"(r) : "f"(lo), "f"(hi));
    return r;
}
__device__ __forceinline__ float2 unpack2(ull v) {
    float2 r;
    asm("mov.b64 {%0, %1}, %2;" : "=f"(r.x), "=f"(r.y) : "l"(v));
    return r;
}
__device__ __forceinline__ void fma2(ull& d, ull a, ull b) {
    asm("fma.rn.f32x2 %0, %1, %2, %0;" : "+l"(d) : "l"(a), "l"(b));
}

// ---------------- bf16 helpers -------------------------------------------------------
__device__ __forceinline__ unsigned short f2bf(float w) {
    unsigned short r;
    asm("cvt.rn.bf16.f32 %0, %1;" : "=h"(r) : "f"(w));
    return r;
}
__device__ __forceinline__ uint32 bf2pack(float e, float o) {   // lo16 = e, hi16 = o
    uint32 r;
    asm("cvt.rn.bf16x2.f32 %0, %1, %2;" : "=r"(r) : "f"(o), "f"(e));
    return r;
}
__device__ __forceinline__ uint32 smem_u32(const void* p) {
    uint32 a;
    asm("{ .reg .u64 t; cvta.to.shared.u64 t, %1; cvt.u32.u64 %0, t; }" : "=r"(a) : "l"(p));
    return a;
}

// ---------------- mma.sync helpers ---------------------------------------------------
#define LDSM4(r, a) asm volatile( \
    "ldmatrix.sync.aligned.m8n8.x4.shared.b16 {%0,%1,%2,%3}, [%4];" \
    : "=r"((r)[0]), "=r"((r)[1]), "=r"((r)[2]), "=r"((r)[3]) : "r"(a))

#define MMA16(c, a, b0, b1) asm volatile( \
    "mma.sync.aligned.m16n8k16.row.col.f32.bf16.bf16.f32 " \
    "{%0,%1,%2,%3}, {%4,%5,%6,%7}, {%8,%9}, {%0,%1,%2,%3};" \
    : "+f"((c)[0]), "+f"((c)[1]), "+f"((c)[2]), "+f"((c)[3]) \
    : "r"((a)[0]), "r"((a)[1]), "r"((a)[2]), "r"((a)[3]), "r"(b0), "r"(b1))

// ---------------- zero stat buckets --------------------------------------------------
__global__ void k_zero_stats() {
    int n = NBUCK * NCH;
    for (int i = blockIdx.x * blockDim.x + threadIdx.x; i < n; i += gridDim.x * blockDim.x) {
        ((double*)g_sumB)[i] = 0.0;
        ((double*)g_sqB)[i]  = 0.0;
    }
}

// ---------------- prep: Wd^T -> bf16 hi/lo [o][k] -----------------------------------
__global__ void k_prepwd(const float* __restrict__ Wd) {
    int idx = blockIdx.x * 256 + threadIdx.x;
    if (idx < A2C * A2C) {
        int k = idx >> 7, o = idx & 127;
        float w = Wd[idx];
        unsigned short h = f2bf(w);
        float hf = __uint_as_float((uint32)h << 16);
        unsigned short l = f2bf(w - hf);
        g_wbhi[o * A2C + k] = h;
        g_wblo[o * A2C + k] = l;
    }
}

// ---------------- pass 1: stats of h1 ------------------------------------------------
__global__ void k_stats1(const float* __restrict__ x,
                         const float* __restrict__ W1,
                         const float* __restrict__ b1, int V) {
    int N = V * PP;
    float lsum[C1], lsq[C1];
    #pragma unroll
    for (int u = 0; u < C1; u++) { lsum[u] = 0.f; lsq[u] = 0.f; }
    for (int r = blockIdx.x * blockDim.x + threadIdx.x; r < N; r += gridDim.x * blockDim.x) {
        float xv[CIN];
        #pragma unroll
        for (int c = 0; c < CIN; c++) xv[c] = x[(size_t)r * CIN + c];
        #pragma unroll
        for (int u = 0; u < C1; u++) {
            float h = b1[u];
            #pragma unroll
            for (int c = 0; c < CIN; c++) h = fmaf(xv[c], W1[c * C1 + u], h);
            lsum[u] += h; lsq[u] += h * h;
        }
    }
    __shared__ float ssum[C1], ssq[C1];
    if (threadIdx.x < C1) { ssum[threadIdx.x] = 0.f; ssq[threadIdx.x] = 0.f; }
    __syncthreads();
    #pragma unroll
    for (int u = 0; u < C1; u++) { atomicAdd(&ssum[u], lsum[u]); atomicAdd(&ssq[u], lsq[u]); }
    __syncthreads();
    if (threadIdx.x < C1) {
        int b = blockIdx.x & (NBUCK - 1);
        atomicAdd(&g_sumB[b][threadIdx.x], (double)ssum[threadIdx.x]);
        atomicAdd(&g_sqB [b][threadIdx.x], (double)ssq [threadIdx.x]);
    }
}

// ---------------- finalize BN params (parallel: grid=nc, block=64 buckets) ----------
__global__ void k_finalize(const float* __restrict__ g, const float* __restrict__ be,
                           int off, int nc, double invN) {
    int u = blockIdx.x;
    int b = threadIdx.x;
    __shared__ double ss[64], qq[64];
    ss[b] = g_sumB[b][off + u];
    qq[b] = g_sqB [b][off + u];
    __syncthreads();
    #pragma unroll
    for (int s = 32; s > 0; s >>= 1) {
        if (b < s) { ss[b] += ss[b + s]; qq[b] += qq[b + s]; }
        __syncthreads();
    }
    if (b == 0) {
        double m   = ss[0] * invN;
        double var = qq[0] * invN - m * m;
        float  sc  = g[u] * rsqrtf((float)var + 1e-5f);
        g_scale[off + u] = sc;
        g_shift[off + u] = (float)((double)be[u] - m * (double)sc);
    }
}

// ---------------- pass 2: BN1+relu, max; HALVED h2 GEMM -> g_h2 ----------------------
__global__ void __launch_bounds__(128) k_vfe1(const float* __restrict__ x,
                       const float* __restrict__ W1, const float* __restrict__ b1,
                       const float* __restrict__ W2, const float* __restrict__ b2, int V) {
    int v = blockIdx.x;
    if (v >= V) return;
    int t = threadIdx.x;

    __shared__ float  s_x[PP * CIN];
    __shared__ float  s_keep[PP + 1];
    __shared__ float  s_h1[PP * C1];
    __shared__ float  s_m1[C1];
    __shared__ float  s_C[C2];
    __shared__ float2 s_a1p[C1 * NP1];
    __shared__ float  s_w2[A1C * C2];
    __shared__ float  s_rs[4 * C2], s_rq[4 * C2];

    const float* xb = x + (size_t)v * (PP * CIN);
    for (int i = t; i < PP * CIN; i += 128) s_x[i] = xb[i];
    for (int i = t; i < A1C * C2; i += 128) s_w2[i] = W2[i];
    __syncthreads();

    if (t < PP) {
        float s = 0.f;
        #pragma unroll
        for (int c = 0; c < CIN; c++) s += s_x[t * CIN + c];
        float k = (s != 0.0f) ? 1.0f : 0.0f;
        s_keep[t] = k;
        g_keep[(size_t)v * PP + t] = k;
    }
    __syncthreads();

    for (int i = t; i < PP * C1; i += 128) {
        int p = i >> 4, u = i & 15;
        float h = b1[u];
        #pragma unroll
        for (int c = 0; c < CIN; c++) h = fmaf(s_x[p * CIN + c], W1[c * C1 + u], h);
        h = fmaf(h, g_scale[u], g_shift[u]);
        s_h1[i] = fmaxf(h, 0.0f);
    }
    __syncthreads();

    if (t < C1) {
        float m = s_h1[t];
        #pragma unroll 7
        for (int p = 1; p < PP; p++) m = fmaxf(m, s_h1[p * C1 + t]);
        s_m1[t] = m;
    }
    __syncthreads();

    for (int i = t; i < C1 * NP1; i += 128) {
        int k = i / NP1, pr = i % NP1;
        int p0 = 2 * pr, p1 = p0 + 1;
        float u0 = 0.f, u1 = 0.f;
        if (p0 < PP) u0 = s_h1[p0 * C1 + k] * s_keep[p0];
        if (p1 < PP) u1 = s_h1[p1 * C1 + k] * s_keep[p1];
        s_a1p[i] = make_float2(u0, u1);
    }
    if (t < C2) {
        float c = 0.f;
        #pragma unroll
        for (int k = 0; k < C1; k++) c = fmaf(s_m1[k], s_w2[(C1 + k) * C2 + t], c);
        s_C[t] = c;
    }
    __syncthreads();

    int lane = t & 31, pg = t >> 5;
    int og = lane * 2;
    ull acc[5][2];
    #pragma unroll
    for (int n = 0; n < 5; n++) { acc[n][0] = 0ULL; acc[n][1] = 0ULL; }

    #pragma unroll 4
    for (int k = 0; k < C1; k++) {
        float2 w = *(const float2*)&s_w2[k * C2 + og];
        ull w0 = pack2(w.x, w.x), w1 = pack2(w.y, w.y);
        const ull* ap = (const ull*)&s_a1p[k * NP1 + pg * 5];
        #pragma unroll
        for (int n = 0; n < 5; n++) {
            ull a = ap[n];
            fma2(acc[n][0], a, w0);
            fma2(acc[n][1], a, w1);
        }
    }

    float C0 = s_C[og], C1v = s_C[og + 1];
    float b0 = b2[og],  b1s = b2[og + 1];
    float ls0 = 0.f, lq0 = 0.f, ls1 = 0.f, lq1 = 0.f;
    float* h2g = g_h2 + (size_t)v * (PP * C2);
    #pragma unroll
    for (int n = 0; n < 5; n++) {
        int pr = pg * 5 + n;
        if (pr < 18) {
            int p0 = 2 * pr, p1 = p0 + 1;
            float2 r0 = unpack2(acc[n][0]);
            float2 r1 = unpack2(acc[n][1]);
            float k0 = s_keep[p0];
            float h00 = fmaf(k0, r0.x + C0,  b0);
            float h01 = fmaf(k0, r1.x + C1v, b1s);
            *(float2*)&h2g[p0 * C2 + og] = make_float2(h00, h01);
            ls0 += h00; lq0 += h00 * h00;
            ls1 += h01; lq1 += h01 * h01;
            if (p1 < PP) {
                float k1 = s_keep[p1];
                float h10 = fmaf(k1, r0.y + C0,  b0);
                float h11 = fmaf(k1, r1.y + C1v, b1s);
                *(float2*)&h2g[p1 * C2 + og] = make_float2(h10, h11);
                ls0 += h10; lq0 += h10 * h10;
                ls1 += h11; lq1 += h11 * h11;
            }
        }
    }
    s_rs[pg * C2 + og] = ls0; s_rs[pg * C2 + og + 1] = ls1;
    s_rq[pg * C2 + og] = lq0; s_rq[pg * C2 + og + 1] = lq1;
    __syncthreads();
    if (t < C2) {
        float S = s_rs[t] + s_rs[C2 + t] + s_rs[2 * C2 + t] + s_rs[3 * C2 + t];
        float Q = s_rq[t] + s_rq[C2 + t] + s_rq[2 * C2 + t] + s_rq[3 * C2 + t];
        int b = v & (NBUCK - 1);
        atomicAdd(&g_sumB[b][C1 + t], (double)S);
        atomicAdd(&g_sqB [b][C1 + t], (double)Q);
    }
}

// ---------------- pass 3: mma.sync GEMM; register-prefetch pipeline ------------------
#define AST   136
#define O_BHI 0
#define O_BLO 8704
#define O_SC  17408
#define O_SH  17472
#define O_BD  17536
#define O_GRP 17664
#define GA_HI 0
#define GA_LO 3264
#define GMM   6528
#define GM2   7552
#define GKEEP 7616              // double-buffered [2][48]
#define GSS   7712
#define GSQ   7840
#define GRPF  7968
#define SM3_BYTES ((O_GRP + NGRP * GRPF) * 4)

#define GBAR() asm volatile("bar.sync %0, %1;" :: "r"(gi + 1), "r"(GT) : "memory")

__global__ void __launch_bounds__(T2V, 1) k_vfe2(const float* __restrict__ bd, int V) {
    extern __shared__ float sm3[];
    int t = threadIdx.x;

    float* s_sc = sm3 + O_SC;
    float* s_sh = sm3 + O_SH;
    float* s_bd = sm3 + O_BD;

    {
        uint32* dBh = (uint32*)(sm3 + O_BHI);
        uint32* dBl = (uint32*)(sm3 + O_BLO);
        const uint32* sBh = (const uint32*)g_wbhi;
        const uint32* sBl = (const uint32*)g_wblo;
        for (int i = t; i < A2C * 64; i += T2V) {
            int o = i >> 6, k2 = i & 63;
            dBh[o * 68 + k2] = sBh[i];
            dBl[o * 68 + k2] = sBl[i];
        }
    }
    if (t < C2)  { s_sc[t] = g_scale[C1 + t]; s_sh[t] = g_shift[C1 + t]; }
    if (t < 128) s_bd[t] = bd[t];

    int gi = t >> 7;
    int lt = t & 127;

    float* grp    = sm3 + O_GRP + gi * GRPF;
    uint32* aHi32 = (uint32*)(grp + GA_HI);
    uint32* aLo32 = (uint32*)(grp + GA_LO);
    float* s_mm   = grp + GMM;
    float* s_m2   = grp + GM2;
    float* s_keep = grp + GKEEP;
    float* s_Ss   = grp + GSS;
    float* s_Sq   = grp + GSQ;

    if (lt < 128) { s_Ss[lt] = 0.f; s_Sq[lt] = 0.f; }
    for (int i = lt; i < 13 * 68; i += GT) {
        int row = 35 + i / 68, cu = i % 68;
        aHi32[row * 68 + cu] = 0u;
        aLo32[row * 68 + cu] = 0u;
    }

    uint32 aHiB = smem_u32(grp + GA_HI);
    uint32 aLoB = smem_u32(grp + GA_LO);
    uint32 bHiB = smem_u32(sm3 + O_BHI);
    uint32 bLoB = smem_u32(sm3 + O_BLO);

    int wrp = lt >> 5, lane = lt & 31;
    int n0 = wrp * 32;
    int lrow = lane & 15, lcolA = (lane >> 4) << 3;
    int q8 = lane >> 3, r8 = lane & 7;
    uint32 aOff = (uint32)(lrow * AST + lcolA) * 2u;
    uint32 bOff = (uint32)((n0 + ((q8 >> 1) << 3) + r8) * AST + ((q8 & 1) << 3)) * 2u;

    // ---- priming prefetch for first voxel (no s_sc dependence) ----
    int v0 = blockIdx.x * NGRP + gi;
    float4 pf[5];
    int kb = 0;
    if (v0 < V) {
        const float4* src = (const float4*)(g_h2 + (size_t)v0 * (PP * C2));
        #pragma unroll
        for (int j = 0; j < 5; j++) {
            int i = lt + 128 * j;
            if (i < 16 * PP) pf[j] = src[i];
        }
        if (lt < 48) s_keep[lt] = (lt < PP) ? g_keep[(size_t)v0 * PP + lt] : 0.f;
    }
    __syncthreads();   // orders s_sc/s_sh/s_bd/B-staging before ALL reads below

    int c4 = (lt & 15) * 4;
    float4 scv = *(const float4*)(s_sc + c4);
    float4 shv = *(const float4*)(s_sh + c4);

    for (int v = v0; v < V; v += NSTREAM) {
        const float* kslot = s_keep + kb * 48;

        // ---- phase 1: convert prefetched h2 -> A lower (bf16 hi/lo); raw min/max ----
        {
            float rmx[4], rmn[4];
            #pragma unroll
            for (int e = 0; e < 4; e++) { rmx[e] = -3.4e38f; rmn[e] = 3.4e38f; }
            #pragma unroll
            for (int j = 0; j < 5; j++) {
                int i = lt + 128 * j;
                if (i < 16 * PP) {
                    float4 h = pf[j];
                    int row = i >> 4;
                    float kp = kslot[row];
                    rmx[0] = fmaxf(rmx[0], h.x); rmn[0] = fminf(rmn[0], h.x);
                    rmx[1] = fmaxf(rmx[1], h.y); rmn[1] = fminf(rmn[1], h.y);
                    rmx[2] = fmaxf(rmx[2], h.z); rmn[2] = fminf(rmn[2], h.z);
                    rmx[3] = fmaxf(rmx[3], h.w); rmn[3] = fminf(rmn[3], h.w);
                    float ax = fmaxf(fmaf(h.x, scv.x, shv.x), 0.f) * kp;
                    float ay = fmaxf(fmaf(h.y, scv.y, shv.y), 0.f) * kp;
                    float az = fmaxf(fmaf(h.z, scv.z, shv.z), 0.f) * kp;
                    float aw = fmaxf(fmaf(h.w, scv.w, shv.w), 0.f) * kp;
                    uint32 hi01 = bf2pack(ax, ay);
                    uint32 hi23 = bf2pack(az, aw);
                    float rx = ax - __uint_as_float(hi01 << 16);
                    float ry = ay - __uint_as_float(hi01 & 0xffff0000u);
                    float rz = az - __uint_as_float(hi23 << 16);
                    float rw = aw - __uint_as_float(hi23 & 0xffff0000u);
                    uint32 lo01 = bf2pack(rx, ry);
                    uint32 lo23 = bf2pack(rz, rw);
                    int u32i = row * 68 + (i & 15) * 2;
                    aHi32[u32i] = hi01; aHi32[u32i + 1] = hi23;
                    aLo32[u32i] = lo01; aLo32[u32i + 1] = lo23;
                }
            }
            float* mm = s_mm + (lt >> 4) * 128 + (lt & 15) * 8;
            #pragma unroll
            for (int e = 0; e < 4; e++) { mm[e] = rmx[e]; mm[4 + e] = rmn[e]; }
        }
        GBAR();

        // ---- phase 2: m2 finalize ----
        if (lt < C2) {
            int cg = lt >> 2, r = lt & 3;
            float MX = -3.4e38f, MN = 3.4e38f;
            #pragma unroll
            for (int w = 0; w < 8; w++) {
                MX = fmaxf(MX, s_mm[w * 128 + cg * 8 + r]);
                MN = fminf(MN, s_mm[w * 128 + cg * 8 + 4 + r]);
            }
            float sc = s_sc[lt];
            float sel = (sc >= 0.f) ? MX : MN;
            s_m2[lt] = fmaxf(fmaf(sel, sc, s_sh[lt]), 0.f);
        }
        GBAR();

        // ---- phase 3: A upper = keep*m2; prefetch next voxel into regs/alt keep ----
        for (int idx = lt; idx < PP * 32; idx += GT) {
            int row = idx >> 5, c2 = idx & 31;
            float kp = kslot[row];
            float a0 = kp * s_m2[2 * c2];
            float a1 = kp * s_m2[2 * c2 + 1];
            uint32 hi = bf2pack(a0, a1);
            float r0 = a0 - __uint_as_float(hi << 16);
            float r1 = a1 - __uint_as_float(hi & 0xffff0000u);
            uint32 lo = bf2pack(r0, r1);
            int u32i = row * 68 + 32 + c2;
            aHi32[u32i] = hi;
            aLo32[u32i] = lo;
        }
        {
            int vn = v + NSTREAM;
            if (vn < V) {
                const float4* src = (const float4*)(g_h2 + (size_t)vn * (PP * C2));
                #pragma unroll
                for (int j = 0; j < 5; j++) {
                    int i = lt + 128 * j;
                    if (i < 16 * PP) pf[j] = src[i];
                }
                if (lt < 48)
                    s_keep[(kb ^ 1) * 48 + lt] = (lt < PP) ? g_keep[(size_t)vn * PP + lt] : 0.f;
            }
        }
        GBAR();

        // ---- phase 4: GEMM via mma.sync (HH, HL, LH) ----
        float acc[3][4][4];
        #pragma unroll
        for (int mt = 0; mt < 3; mt++)
            #pragma unroll
            for (int nt = 0; nt < 4; nt++)
                #pragma unroll
                for (int e = 0; e < 4; e++) acc[mt][nt][e] = 0.f;

        #pragma unroll 4
        for (int k0 = 0; k0 < 128; k0 += 16) {
            uint32 ah[3][4], al[3][4], bh[2][4], bl[2][4];
            #pragma unroll
            for (int mt = 0; mt < 3; mt++) {
                uint32 off = aOff + (uint32)(mt * 16 * AST + k0) * 2u;
                LDSM4(ah[mt], aHiB + off);
                LDSM4(al[mt], aLoB + off);
            }
            #pragma unroll
            for (int nh = 0; nh < 2; nh++) {
                uint32 off = bOff + (uint32)(nh * 16 * AST + k0) * 2u;
                LDSM4(bh[nh], bHiB + off);
                LDSM4(bl[nh], bLoB + off);
            }
            #pragma unroll
            for (int mt = 0; mt < 3; mt++) {
                #pragma unroll
                for (int nt = 0; nt < 4; nt++) {
                    const uint32* bhp = bh[nt >> 1];
                    const uint32* blp = bl[nt >> 1];
                    int pe = (nt & 1) * 2;
                    MMA16(acc[mt][nt], ah[mt], bhp[pe], bhp[pe + 1]);
                    MMA16(acc[mt][nt], ah[mt], blp[pe], blp[pe + 1]);
                    MMA16(acc[mt][nt], al[mt], bhp[pe], bhp[pe + 1]);
                }
            }
        }

        // ---- phase 5: register epilogue (+bd), masked stats, shfl reduce ----
        {
            int l4 = lane >> 2;
            bool v2 = (l4 < 3);
            #pragma unroll
            for (int nt = 0; nt < 4; nt++) {
                #pragma unroll
                for (int e = 0; e < 2; e++) {
                    int c = n0 + nt * 8 + 2 * (lane & 3) + e;
                    float bdv = s_bd[c];
                    float h0 = acc[0][nt][e]     + bdv;
                    float h1 = acc[0][nt][e + 2] + bdv;
                    float h2 = acc[1][nt][e]     + bdv;
                    float h3 = acc[1][nt][e + 2] + bdv;
                    float S = h0 + h1 + h2 + h3;
                    float Q = fmaf(h0, h0, fmaf(h1, h1, fmaf(h2, h2, h3 * h3)));
                    float MX = fmaxf(fmaxf(h0, h1), fmaxf(h2, h3));
                    float MN = fminf(fminf(h0, h1), fminf(h2, h3));
                    if (v2) {
                        float h4 = acc[2][nt][e] + bdv;
                        S += h4; Q = fmaf(h4, h4, Q);
                        MX = fmaxf(MX, h4); MN = fminf(MN, h4);
                    }
                    #pragma unroll
                    for (int d = 4; d <= 16; d <<= 1) {
                        S += __shfl_xor_sync(0xffffffffu, S, d);
                        Q += __shfl_xor_sync(0xffffffffu, Q, d);
                        MX = fmaxf(MX, __shfl_xor_sync(0xffffffffu, MX, d));
                        MN = fminf(MN, __shfl_xor_sync(0xffffffffu, MN, d));
                    }
                    if (l4 == 0) {
                        g_max3[(size_t)v * C3 + c] = MX;
                        g_min3[(size_t)v * C3 + c] = MN;
                        s_Ss[c] += S;
                        s_Sq[c] += Q;
                    }
                }
            }
        }
        GBAR();   // A reads done; alt s_keep visible for next phase 1
        kb ^= 1;
    }

    // ---- flush running stats once per group ----
    GBAR();
    {
        int b = (blockIdx.x * NGRP + gi) & (NBUCK - 1);
        atomicAdd(&g_sumB[b][C1 + C2 + lt], (double)s_Ss[lt]);
        atomicAdd(&g_sqB [b][C1 + C2 + lt], (double)s_Sq[lt]);
    }
}

// ---------------- pass 4: BN3 + relu + max (via max/min) + scatter-add ---------------
__global__ void k_scatter(const int* __restrict__ coord, float* __restrict__ out, int V) {
    int v = blockIdx.x;
    if (v >= V) return;
    int u = threadIdx.x;
    float sc = g_scale[C1 + C2 + u];
    float sh = g_shift[C1 + C2 + u];
    float h  = (sc >= 0.0f) ? g_max3[(size_t)v * C3 + u] : g_min3[(size_t)v * C3 + u];
    float val = fmaxf(fmaf(h, sc, sh), 0.0f);
    int cz = coord[v * 3 + 0];
    int cy = coord[v * 3 + 1];
    int cx = coord[v * 3 + 2];
    size_t off = (size_t)u * (DD * HH * WWG) + (size_t)cz * (HH * WWG) + (size_t)cy * WWG + cx;
    atomicAdd(out + off, val);
}

// ---------------- launch ---------------------------------------------------------------
extern "C" void kernel_launch(void* const* d_in, const int* in_sizes, int n_in,
                              void* d_out, int out_size) {
    const float* x     = (const float*)d_in[0];
    const int*   coord = (const int*)  d_in[1];
    const float* W1 = (const float*)d_in[2];
    const float* b1 = (const float*)d_in[3];
    const float* g1 = (const float*)d_in[4];
    const float* be1= (const float*)d_in[5];
    const float* W2 = (const float*)d_in[6];
    const float* b2 = (const float*)d_in[7];
    const float* g2 = (const float*)d_in[8];
    const float* be2= (const float*)d_in[9];
    const float* Wd = (const float*)d_in[10];
    const float* bd = (const float*)d_in[11];
    const float* gd = (const float*)d_in[12];
    const float* bed= (const float*)d_in[13];

    int V = in_sizes[1] / 3;
    if (V > VMAX) V = VMAX;
    double invN = 1.0 / ((double)V * PP);

    cudaFuncSetAttribute(k_vfe2, cudaFuncAttributeMaxDynamicSharedMemorySize, SM3_BYTES);

    cudaMemsetAsync(d_out, 0, (size_t)out_size * sizeof(float), 0);
    k_zero_stats<<<32, 256>>>();
    k_prepwd<<<64, 256>>>(Wd);
    k_stats1<<<592, 256>>>(x, W1, b1, V);
    k_finalize<<<C1, 64>>>(g1, be1, 0, C1, invN);
    k_vfe1<<<V, 128>>>(x, W1, b1, W2, b2, V);
    k_finalize<<<C2, 64>>>(g2, be2, C1, C2, invN);
    k_vfe2<<<GRID2, T2V, SM3_BYTES>>>(bd, V);
    k_finalize<<<C3, 64>>>(gd, bed, C1 + C2, C3, invN);
    k_scatter<<<V, 128>>>(coord, (float*)d_out, V);
}